// round 1
// baseline (speedup 1.0000x reference)
#include <cuda_runtime.h>
#include <math.h>

#define D_MODEL 1024
#define B_SZ    8
#define S_LEN   2048
#define ROWS    (B_SZ * S_LEN)   /* 16384 */

// ---------------- scratch (device globals; no allocation allowed) ----------
__device__ float g_h[(size_t)ROWS * D_MODEL];            //  64 MB (ln1 out, reused for ln2 out)
__device__ float g_qkv[(size_t)ROWS * 3 * D_MODEL];      // 192 MB
__device__ float g_scores[(size_t)B_SZ * S_LEN * S_LEN]; // 128 MB
__device__ float g_x2[(size_t)ROWS * D_MODEL];           //  64 MB (residual out)
__device__ float g_fc[(size_t)ROWS * 4 * D_MODEL];       // 256 MB

// ---------------- reductions ----------------
__device__ __forceinline__ float block_sum(float v) {
    __shared__ float sh[8];
    int lane = threadIdx.x & 31, w = threadIdx.x >> 5;
    #pragma unroll
    for (int o = 16; o; o >>= 1) v += __shfl_xor_sync(0xffffffffu, v, o);
    if (lane == 0) sh[w] = v;
    __syncthreads();
    if (w == 0) {
        v = sh[lane & 7];
        #pragma unroll
        for (int o = 4; o; o >>= 1) v += __shfl_xor_sync(0xffffffffu, v, o);
        if (lane == 0) sh[0] = v;
    }
    __syncthreads();
    float r = sh[0];
    __syncthreads();
    return r;
}

__device__ __forceinline__ float block_max(float v) {
    __shared__ float sh[8];
    int lane = threadIdx.x & 31, w = threadIdx.x >> 5;
    #pragma unroll
    for (int o = 16; o; o >>= 1) v = fmaxf(v, __shfl_xor_sync(0xffffffffu, v, o));
    if (lane == 0) sh[w] = v;
    __syncthreads();
    if (w == 0) {
        v = sh[lane & 7];
        #pragma unroll
        for (int o = 4; o; o >>= 1) v = fmaxf(v, __shfl_xor_sync(0xffffffffu, v, o));
        if (lane == 0) sh[0] = v;
    }
    __syncthreads();
    float r = sh[0];
    __syncthreads();
    return r;
}

__device__ __forceinline__ float gelu_exact(float x) {
    return 0.5f * x * (1.0f + erff(x * 0.70710678118654752f));
}

// ---------------- LayerNorm: one block (256 thr) per row of 1024 ----------
__global__ void ln_kernel(const float* __restrict__ x, const float* __restrict__ w,
                          const float* __restrict__ b, float* __restrict__ out) {
    size_t row = blockIdx.x;
    const float4* xr = (const float4*)(x + row * D_MODEL);
    float4 v = xr[threadIdx.x];
    float s  = v.x + v.y + v.z + v.w;
    float ss = v.x * v.x + v.y * v.y + v.z * v.z + v.w * v.w;
    s  = block_sum(s);
    ss = block_sum(ss);
    float mu  = s * (1.0f / D_MODEL);
    float var = ss * (1.0f / D_MODEL) - mu * mu;
    float inv = rsqrtf(var + 1e-5f);
    float4 wv = ((const float4*)w)[threadIdx.x];
    float4 bv = ((const float4*)b)[threadIdx.x];
    float4 o;
    o.x = (v.x - mu) * inv * wv.x + bv.x;
    o.y = (v.y - mu) * inv * wv.y + bv.y;
    o.z = (v.z - mu) * inv * wv.z + bv.z;
    o.w = (v.w - mu) * inv * wv.w + bv.w;
    ((float4*)(out + row * D_MODEL))[threadIdx.x] = o;
}

// ---------------- Softmax: one block (256 thr) per row of 2048, in-place ---
__global__ void softmax_kernel(float* __restrict__ sc) {
    size_t row = blockIdx.x;
    float* p = sc + row * (size_t)S_LEN;
    float4 v0 = ((float4*)p)[threadIdx.x];
    float4 v1 = ((float4*)p)[threadIdx.x + 256];
    float m = fmaxf(fmaxf(fmaxf(v0.x, v0.y), fmaxf(v0.z, v0.w)),
                    fmaxf(fmaxf(v1.x, v1.y), fmaxf(v1.z, v1.w)));
    m = block_max(m);
    v0.x = expf(v0.x - m); v0.y = expf(v0.y - m);
    v0.z = expf(v0.z - m); v0.w = expf(v0.w - m);
    v1.x = expf(v1.x - m); v1.y = expf(v1.y - m);
    v1.z = expf(v1.z - m); v1.w = expf(v1.w - m);
    float s = v0.x + v0.y + v0.z + v0.w + v1.x + v1.y + v1.z + v1.w;
    s = block_sum(s);
    float inv = 1.0f / s;
    v0.x *= inv; v0.y *= inv; v0.z *= inv; v0.w *= inv;
    v1.x *= inv; v1.y *= inv; v1.z *= inv; v1.w *= inv;
    ((float4*)p)[threadIdx.x]       = v0;
    ((float4*)p)[threadIdx.x + 256] = v1;
}

// ---------------- SGEMM: 128x128x16 tile, 256 thr, 8x8 microtile ----------
// C = act(alpha * A @ B(^T) + bias) (+ residual)
// All of M, N must be multiples of 128; K multiple of 16.
template <bool TRANSB, bool BIAS, int ACT, bool RES>
__global__ __launch_bounds__(256, 2)
void sgemm_kernel(const float* __restrict__ A, const float* __restrict__ B,
                  const float* __restrict__ bias, const float* __restrict__ res,
                  float* __restrict__ C,
                  int K, int lda, int ldb, int ldc, int ldres,
                  size_t strideA, size_t strideB, size_t strideC, size_t strideRes,
                  float alpha) {
    __shared__ float As[16][128];
    __shared__ float Bs[16][128];

    const int bn = blockIdx.x, bm = blockIdx.y, bz = blockIdx.z;
    const float* Ab = A + strideA * bz;
    const float* Bb = B + strideB * bz;
    float*       Cb = C + strideC * bz;

    const int tid = threadIdx.x;
    const int tx  = tid & 15;   // 0..15 -> N
    const int ty  = tid >> 4;   // 0..15 -> M

    float acc[8][8];
    #pragma unroll
    for (int i = 0; i < 8; i++)
        #pragma unroll
        for (int j = 0; j < 8; j++) acc[i][j] = 0.0f;

    for (int k0 = 0; k0 < K; k0 += 16) {
        // A tile: 128 rows x 16 cols, stored transposed As[k][m]
        #pragma unroll
        for (int it = 0; it < 2; it++) {
            int item = tid + it * 256;      // 0..511
            int r  = item >> 2;             // 0..127
            int c4 = item & 3;              // 0..3
            float4 v = *(const float4*)(Ab + (size_t)(bm * 128 + r) * lda + k0 + c4 * 4);
            As[c4 * 4 + 0][r] = v.x;
            As[c4 * 4 + 1][r] = v.y;
            As[c4 * 4 + 2][r] = v.z;
            As[c4 * 4 + 3][r] = v.w;
        }
        if (TRANSB) {
            // B is [N, K] row-major; tile 128(n) x 16(k)
            #pragma unroll
            for (int it = 0; it < 2; it++) {
                int item = tid + it * 256;
                int n  = item >> 2;
                int c4 = item & 3;
                float4 v = *(const float4*)(Bb + (size_t)(bn * 128 + n) * ldb + k0 + c4 * 4);
                Bs[c4 * 4 + 0][n] = v.x;
                Bs[c4 * 4 + 1][n] = v.y;
                Bs[c4 * 4 + 2][n] = v.z;
                Bs[c4 * 4 + 3][n] = v.w;
            }
        } else {
            // B is [K, N] row-major; tile 16(k) x 128(n)
            #pragma unroll
            for (int it = 0; it < 2; it++) {
                int item = tid + it * 256;
                int r  = item >> 5;          // 0..15
                int c4 = item & 31;          // 0..31
                float4 v = *(const float4*)(Bb + (size_t)(k0 + r) * ldb + bn * 128 + c4 * 4);
                *(float4*)&Bs[r][c4 * 4] = v;
            }
        }
        __syncthreads();

        #pragma unroll
        for (int kk = 0; kk < 16; kk++) {
            float a[8], b[8];
            *(float4*)&a[0] = *(const float4*)&As[kk][ty * 8];
            *(float4*)&a[4] = *(const float4*)&As[kk][ty * 8 + 4];
            *(float4*)&b[0] = *(const float4*)&Bs[kk][tx * 8];
            *(float4*)&b[4] = *(const float4*)&Bs[kk][tx * 8 + 4];
            #pragma unroll
            for (int i = 0; i < 8; i++)
                #pragma unroll
                for (int j = 0; j < 8; j++) acc[i][j] += a[i] * b[j];
        }
        __syncthreads();
    }

    // epilogue
    #pragma unroll
    for (int i = 0; i < 8; i++) {
        int row = bm * 128 + ty * 8 + i;
        #pragma unroll
        for (int j = 0; j < 8; j += 4) {
            int col = bn * 128 + tx * 8 + j;
            float4 o;
            float* po = &o.x;
            float4 rv;
            if (RES) rv = *(const float4*)(res + strideRes * bz + (size_t)row * ldres + col);
            const float* prv = &rv.x;
            #pragma unroll
            for (int jj = 0; jj < 4; jj++) {
                float v = acc[i][j + jj] * alpha;
                if (BIAS) v += bias[col + jj];
                if (ACT == 1) v = gelu_exact(v);
                if (RES) v += prv[jj];
                po[jj] = v;
            }
            *(float4*)(Cb + (size_t)row * ldc + col) = o;
        }
    }
}

// ---------------- launch ----------------
extern "C" void kernel_launch(void* const* d_in, const int* in_sizes, int n_in,
                              void* d_out, int out_size) {
    const float* x      = (const float*)d_in[0];
    const float* ln1_w  = (const float*)d_in[1];
    const float* ln1_b  = (const float*)d_in[2];
    const float* W_attn = (const float*)d_in[3];
    const float* b_attn = (const float*)d_in[4];
    const float* ln2_w  = (const float*)d_in[5];
    const float* ln2_b  = (const float*)d_in[6];
    const float* W_fc   = (const float*)d_in[7];
    const float* b_fc   = (const float*)d_in[8];
    const float* W_proj = (const float*)d_in[9];
    const float* b_proj = (const float*)d_in[10];
    float* out = (float*)d_out;

    void* p;
    cudaGetSymbolAddress(&p, g_h);      float* h   = (float*)p;
    cudaGetSymbolAddress(&p, g_qkv);    float* qkv = (float*)p;
    cudaGetSymbolAddress(&p, g_scores); float* sc  = (float*)p;
    cudaGetSymbolAddress(&p, g_x2);     float* x2  = (float*)p;
    cudaGetSymbolAddress(&p, g_fc);     float* fcb = (float*)p;

    dim3 blk(256);

    // 1) h = LN1(x)
    ln_kernel<<<ROWS, blk>>>(x, ln1_w, ln1_b, h);

    // 2) qkv = h @ W_attn + b_attn     [16384,3072]
    sgemm_kernel<false, true, 0, false><<<dim3(3072 / 128, ROWS / 128, 1), blk>>>(
        h, W_attn, b_attn, nullptr, qkv,
        1024, 1024, 3072, 3072, 0, 0, 0, 0, 0, 1.0f);

    // 3) scores = (q @ k^T) / sqrt(D)  batched over B=8, [2048,2048] each
    sgemm_kernel<true, false, 0, false><<<dim3(16, 16, 8), blk>>>(
        qkv, qkv + 1024, nullptr, nullptr, sc,
        1024, 3072, 3072, 2048, 0,
        (size_t)S_LEN * 3072, (size_t)S_LEN * 3072, (size_t)S_LEN * S_LEN, 0,
        0.03125f /* 1/sqrt(1024) */);

    // 4) softmax rows (in-place)
    softmax_kernel<<<ROWS, blk>>>(sc);

    // 5) x2 = x + attn @ v             batched, [2048,1024] each
    sgemm_kernel<false, false, 0, true><<<dim3(8, 16, 8), blk>>>(
        sc, qkv + 2048, nullptr, x, x2,
        2048, 2048, 3072, 1024, 1024,
        (size_t)S_LEN * S_LEN, (size_t)S_LEN * 3072,
        (size_t)S_LEN * 1024, (size_t)S_LEN * 1024, 1.0f);

    // 6) h = LN2(x2)
    ln_kernel<<<ROWS, blk>>>(x2, ln2_w, ln2_b, h);

    // 7) fc = gelu(h @ W_fc + b_fc)    [16384,4096]
    sgemm_kernel<false, true, 1, false><<<dim3(4096 / 128, ROWS / 128, 1), blk>>>(
        h, W_fc, b_fc, nullptr, fcb,
        1024, 1024, 4096, 4096, 0, 0, 0, 0, 0, 1.0f);

    // 8) out = fc @ W_proj + b_proj    [16384,1024]
    sgemm_kernel<false, true, 0, false><<<dim3(1024 / 128, ROWS / 128, 1), blk>>>(
        fcb, W_proj, b_proj, nullptr, out,
        4096, 4096, 1024, 1024, 0, 0, 0, 0, 0, 1.0f);
}

// round 2
// speedup vs baseline: 2.7907x; 2.7907x over previous
#include <cuda_runtime.h>
#include <math.h>
#include <stdint.h>

#define D_MODEL 1024
#define B_SZ    8
#define S_LEN   2048
#define ROWS    (B_SZ * S_LEN)   /* 16384 */

// ---------------- scratch (device globals; no allocation allowed) ----------
__device__ float g_h[(size_t)ROWS * D_MODEL];            //  64 MB
__device__ float g_qkv[(size_t)ROWS * 3 * D_MODEL];      // 192 MB
__device__ float g_scores[(size_t)B_SZ * S_LEN * S_LEN]; // 128 MB
__device__ float g_x2[(size_t)ROWS * D_MODEL];           //  64 MB
__device__ float g_fc[(size_t)ROWS * 4 * D_MODEL];       // 256 MB

// ---------------- helpers ----------------
__device__ __forceinline__ float tf32_rna(float x) {
    uint32_t u;
    asm("cvt.rna.tf32.f32 %0, %1;" : "=r"(u) : "f"(x));
    return __uint_as_float(u);
}

__device__ __forceinline__ float block_sum(float v) {
    __shared__ float sh[8];
    int lane = threadIdx.x & 31, w = threadIdx.x >> 5;
    #pragma unroll
    for (int o = 16; o; o >>= 1) v += __shfl_xor_sync(0xffffffffu, v, o);
    if (lane == 0) sh[w] = v;
    __syncthreads();
    if (w == 0) {
        v = sh[lane & 7];
        #pragma unroll
        for (int o = 4; o; o >>= 1) v += __shfl_xor_sync(0xffffffffu, v, o);
        if (lane == 0) sh[0] = v;
    }
    __syncthreads();
    float r = sh[0];
    __syncthreads();
    return r;
}

__device__ __forceinline__ float block_max(float v) {
    __shared__ float sh[8];
    int lane = threadIdx.x & 31, w = threadIdx.x >> 5;
    #pragma unroll
    for (int o = 16; o; o >>= 1) v = fmaxf(v, __shfl_xor_sync(0xffffffffu, v, o));
    if (lane == 0) sh[w] = v;
    __syncthreads();
    if (w == 0) {
        v = sh[lane & 7];
        #pragma unroll
        for (int o = 4; o; o >>= 1) v = fmaxf(v, __shfl_xor_sync(0xffffffffu, v, o));
        if (lane == 0) sh[0] = v;
    }
    __syncthreads();
    float r = sh[0];
    __syncthreads();
    return r;
}

__device__ __forceinline__ float gelu_exact(float x) {
    return 0.5f * x * (1.0f + erff(x * 0.70710678118654752f));
}

// ---------------- LayerNorm: one block (256 thr) per row of 1024 ----------
__global__ void ln_kernel(const float* __restrict__ x, const float* __restrict__ w,
                          const float* __restrict__ b, float* __restrict__ out) {
    size_t row = blockIdx.x;
    const float4* xr = (const float4*)(x + row * D_MODEL);
    float4 v = xr[threadIdx.x];
    float s  = v.x + v.y + v.z + v.w;
    float ss = v.x * v.x + v.y * v.y + v.z * v.z + v.w * v.w;
    s  = block_sum(s);
    ss = block_sum(ss);
    float mu  = s * (1.0f / D_MODEL);
    float var = ss * (1.0f / D_MODEL) - mu * mu;
    float inv = rsqrtf(var + 1e-5f);
    float4 wv = ((const float4*)w)[threadIdx.x];
    float4 bv = ((const float4*)b)[threadIdx.x];
    float4 o;
    o.x = (v.x - mu) * inv * wv.x + bv.x;
    o.y = (v.y - mu) * inv * wv.y + bv.y;
    o.z = (v.z - mu) * inv * wv.z + bv.z;
    o.w = (v.w - mu) * inv * wv.w + bv.w;
    ((float4*)(out + row * D_MODEL))[threadIdx.x] = o;
}

// ---------------- Softmax: one block (256 thr) per row of 2048, in-place ---
__global__ void softmax_kernel(float* __restrict__ sc) {
    size_t row = blockIdx.x;
    float* p = sc + row * (size_t)S_LEN;
    float4 v0 = ((float4*)p)[threadIdx.x];
    float4 v1 = ((float4*)p)[threadIdx.x + 256];
    float m = fmaxf(fmaxf(fmaxf(v0.x, v0.y), fmaxf(v0.z, v0.w)),
                    fmaxf(fmaxf(v1.x, v1.y), fmaxf(v1.z, v1.w)));
    m = block_max(m);
    v0.x = expf(v0.x - m); v0.y = expf(v0.y - m);
    v0.z = expf(v0.z - m); v0.w = expf(v0.w - m);
    v1.x = expf(v1.x - m); v1.y = expf(v1.y - m);
    v1.z = expf(v1.z - m); v1.w = expf(v1.w - m);
    float s = v0.x + v0.y + v0.z + v0.w + v1.x + v1.y + v1.z + v1.w;
    s = block_sum(s);
    float inv = 1.0f / s;
    v0.x *= inv; v0.y *= inv; v0.z *= inv; v0.w *= inv;
    v1.x *= inv; v1.y *= inv; v1.z *= inv; v1.w *= inv;
    ((float4*)p)[threadIdx.x]       = v0;
    ((float4*)p)[threadIdx.x + 256] = v1;
}

// =================== Tensor-core GEMM (tf32 mma.sync) ======================
// C = act(alpha * A @ B(^T) + bias) (+ residual)
// Block tile 128x128x32, 256 threads (8 warps, 4x2), warp tile 32x64.
// A: [M,K] row-major (always). B: [K,N] row-major (!TRANSB) or [N,K] (TRANSB).
// M,N multiples of 128; K multiple of 32.
#define AS_LD 36   /* 32 + 4 pad, floats */
#define BS_LD 132  /* 128 + 4 pad, floats */

template <bool TRANSB, bool BIAS, int ACT, bool RES>
__global__ __launch_bounds__(256, 2)
void mma_gemm(const float* __restrict__ A, const float* __restrict__ B,
              const float* __restrict__ bias, const float* __restrict__ res,
              float* __restrict__ C,
              int K, int lda, int ldb, int ldc, int ldres,
              size_t sA, size_t sB, size_t sC, size_t sR, float alpha) {
    __shared__ float As[128 * AS_LD];   // [m][k] padded
    __shared__ float Bs[4608];          // !TRANSB: [k][n] pad 132 ; TRANSB: [n][k] pad 36

    const int bn = blockIdx.x, bm = blockIdx.y, bz = blockIdx.z;
    const float* Ab = A + sA * bz + (size_t)bm * 128 * lda;
    const float* Bb = B + sB * bz;
    float*       Cb = C + sC * bz;

    const int tid  = threadIdx.x;
    const int lane = tid & 31;
    const int warp = tid >> 5;
    const int wm   = warp >> 1;  // 0..3
    const int wn   = warp & 1;   // 0..1

    // ldmatrix per-lane row selection for A fragments
    const int a_r = (lane & 7) + ((lane >> 3) & 1) * 8;
    const int a_c = (lane >> 4) * 4;

    float acc[2][8][4];
    #pragma unroll
    for (int i = 0; i < 2; i++)
        #pragma unroll
        for (int j = 0; j < 8; j++)
            #pragma unroll
            for (int l = 0; l < 4; l++) acc[i][j][l] = 0.0f;

    for (int k0 = 0; k0 < K; k0 += 32) {
        // ---- stage A: 128(m) x 32(k), float4 per thread x4, tf32-round ----
        #pragma unroll
        for (int it = 0; it < 4; it++) {
            int idx = it * 256 + tid;
            int m = idx >> 3, c = (idx & 7) * 4;
            float4 v = *(const float4*)(Ab + (size_t)m * lda + k0 + c);
            float4 w;
            w.x = tf32_rna(v.x); w.y = tf32_rna(v.y);
            w.z = tf32_rna(v.z); w.w = tf32_rna(v.w);
            *(float4*)&As[m * AS_LD + c] = w;
        }
        // ---- stage B ----
        if (TRANSB) {
            #pragma unroll
            for (int it = 0; it < 4; it++) {
                int idx = it * 256 + tid;
                int n = idx >> 3, c = (idx & 7) * 4;
                float4 v = *(const float4*)(Bb + (size_t)(bn * 128 + n) * ldb + k0 + c);
                float4 w;
                w.x = tf32_rna(v.x); w.y = tf32_rna(v.y);
                w.z = tf32_rna(v.z); w.w = tf32_rna(v.w);
                *(float4*)&Bs[n * AS_LD + c] = w;
            }
        } else {
            #pragma unroll
            for (int it = 0; it < 4; it++) {
                int idx = it * 256 + tid;
                int k = idx >> 5, g = (idx & 31) * 4;
                float4 v = *(const float4*)(Bb + (size_t)(k0 + k) * ldb + bn * 128 + g);
                float4 w;
                w.x = tf32_rna(v.x); w.y = tf32_rna(v.y);
                w.z = tf32_rna(v.z); w.w = tf32_rna(v.w);
                *(float4*)&Bs[k * BS_LD + g] = w;
            }
        }
        __syncthreads();

        // ---- compute: 4 k-steps of m16n8k8 ----
        #pragma unroll
        for (int ks = 0; ks < 4; ks++) {
            uint32_t a[2][4];
            #pragma unroll
            for (int am = 0; am < 2; am++) {
                uint32_t addr = (uint32_t)__cvta_generic_to_shared(
                    &As[(wm * 32 + am * 16 + a_r) * AS_LD + ks * 8 + a_c]);
                asm volatile(
                    "ldmatrix.sync.aligned.m8n8.x4.shared.b16 {%0,%1,%2,%3}, [%4];"
                    : "=r"(a[am][0]), "=r"(a[am][1]), "=r"(a[am][2]), "=r"(a[am][3])
                    : "r"(addr));
            }
            uint32_t b[8][2];
            #pragma unroll
            for (int an = 0; an < 8; an++) {
                int n = wn * 64 + an * 8 + (lane >> 2);
                int k = ks * 8 + (lane & 3);
                float b0, b1;
                if (TRANSB) {
                    b0 = Bs[n * AS_LD + k];
                    b1 = Bs[n * AS_LD + k + 4];
                } else {
                    b0 = Bs[k * BS_LD + n];
                    b1 = Bs[(k + 4) * BS_LD + n];
                }
                b[an][0] = __float_as_uint(b0);
                b[an][1] = __float_as_uint(b1);
            }
            #pragma unroll
            for (int am = 0; am < 2; am++)
                #pragma unroll
                for (int an = 0; an < 8; an++) {
                    asm volatile(
                        "mma.sync.aligned.m16n8k8.row.col.f32.tf32.tf32.f32 "
                        "{%0,%1,%2,%3}, {%4,%5,%6,%7}, {%8,%9}, {%0,%1,%2,%3};"
                        : "+f"(acc[am][an][0]), "+f"(acc[am][an][1]),
                          "+f"(acc[am][an][2]), "+f"(acc[am][an][3])
                        : "r"(a[am][0]), "r"(a[am][1]), "r"(a[am][2]), "r"(a[am][3]),
                          "r"(b[an][0]), "r"(b[an][1]));
                }
        }
        __syncthreads();
    }

    // ---- epilogue ----
    const int q  = lane >> 2;        // 0..7
    const int r2 = (lane & 3) * 2;   // 0,2,4,6
    #pragma unroll
    for (int am = 0; am < 2; am++) {
        int row0 = bm * 128 + wm * 32 + am * 16 + q;
        int row1 = row0 + 8;
        #pragma unroll
        for (int an = 0; an < 8; an++) {
            int col = bn * 128 + wn * 64 + an * 8 + r2;
            float v00 = acc[am][an][0] * alpha;
            float v01 = acc[am][an][1] * alpha;
            float v10 = acc[am][an][2] * alpha;
            float v11 = acc[am][an][3] * alpha;
            if (BIAS) {
                float2 bv = *(const float2*)(bias + col);
                v00 += bv.x; v01 += bv.y; v10 += bv.x; v11 += bv.y;
            }
            if (ACT == 1) {
                v00 = gelu_exact(v00); v01 = gelu_exact(v01);
                v10 = gelu_exact(v10); v11 = gelu_exact(v11);
            }
            if (RES) {
                float2 r0 = *(const float2*)(res + sR * bz + (size_t)row0 * ldres + col);
                float2 r1 = *(const float2*)(res + sR * bz + (size_t)row1 * ldres + col);
                v00 += r0.x; v01 += r0.y; v10 += r1.x; v11 += r1.y;
            }
            *(float2*)(Cb + (size_t)row0 * ldc + col) = make_float2(v00, v01);
            *(float2*)(Cb + (size_t)row1 * ldc + col) = make_float2(v10, v11);
        }
    }
}

// ---------------- launch ----------------
extern "C" void kernel_launch(void* const* d_in, const int* in_sizes, int n_in,
                              void* d_out, int out_size) {
    const float* x      = (const float*)d_in[0];
    const float* ln1_w  = (const float*)d_in[1];
    const float* ln1_b  = (const float*)d_in[2];
    const float* W_attn = (const float*)d_in[3];
    const float* b_attn = (const float*)d_in[4];
    const float* ln2_w  = (const float*)d_in[5];
    const float* ln2_b  = (const float*)d_in[6];
    const float* W_fc   = (const float*)d_in[7];
    const float* b_fc   = (const float*)d_in[8];
    const float* W_proj = (const float*)d_in[9];
    const float* b_proj = (const float*)d_in[10];
    float* out = (float*)d_out;

    void* p;
    cudaGetSymbolAddress(&p, g_h);      float* h   = (float*)p;
    cudaGetSymbolAddress(&p, g_qkv);    float* qkv = (float*)p;
    cudaGetSymbolAddress(&p, g_scores); float* sc  = (float*)p;
    cudaGetSymbolAddress(&p, g_x2);     float* x2  = (float*)p;
    cudaGetSymbolAddress(&p, g_fc);     float* fcb = (float*)p;

    dim3 blk(256);

    // 1) h = LN1(x)
    ln_kernel<<<ROWS, blk>>>(x, ln1_w, ln1_b, h);

    // 2) qkv = h @ W_attn + b_attn     [16384,3072]
    mma_gemm<false, true, 0, false><<<dim3(24, 128, 1), blk>>>(
        h, W_attn, b_attn, nullptr, qkv,
        1024, 1024, 3072, 3072, 0, 0, 0, 0, 0, 1.0f);

    // 3) scores = (q @ k^T) / sqrt(D)  batched over B=8
    mma_gemm<true, false, 0, false><<<dim3(16, 16, 8), blk>>>(
        qkv, qkv + 1024, nullptr, nullptr, sc,
        1024, 3072, 3072, 2048, 0,
        (size_t)S_LEN * 3072, (size_t)S_LEN * 3072, (size_t)S_LEN * S_LEN, 0,
        0.03125f);

    // 4) softmax rows (in-place)
    softmax_kernel<<<ROWS, blk>>>(sc);

    // 5) x2 = x + attn @ v             batched
    mma_gemm<false, false, 0, true><<<dim3(8, 16, 8), blk>>>(
        sc, qkv + 2048, nullptr, x, x2,
        2048, 2048, 3072, 1024, 1024,
        (size_t)S_LEN * S_LEN, (size_t)S_LEN * 3072,
        (size_t)S_LEN * 1024, (size_t)S_LEN * 1024, 1.0f);

    // 6) h = LN2(x2)
    ln_kernel<<<ROWS, blk>>>(x2, ln2_w, ln2_b, h);

    // 7) fc = gelu(h @ W_fc + b_fc)    [16384,4096]
    mma_gemm<false, true, 1, false><<<dim3(32, 128, 1), blk>>>(
        h, W_fc, b_fc, nullptr, fcb,
        1024, 1024, 4096, 4096, 0, 0, 0, 0, 0, 1.0f);

    // 8) out = fc @ W_proj + b_proj    [16384,1024]
    mma_gemm<false, true, 0, false><<<dim3(8, 128, 1), blk>>>(
        fcb, W_proj, b_proj, nullptr, out,
        4096, 4096, 1024, 1024, 0, 0, 0, 0, 0, 1.0f);
}